// round 3
// baseline (speedup 1.0000x reference)
#include <cuda_runtime.h>
#include <cuda_bf16.h>

#define N_NODES 40000
#define N_EDGES 640000
#define D 128

// ---------------- scratch (device globals, referenced by symbol only) ----------------
__device__ float g_h[N_NODES * D];        // GEMM output (per layer)
__device__ float g_y[N_NODES * D];        // layer-1 output
__device__ int   g_deg[N_NODES];          // degree histogram (by dst)
__device__ int   g_rowptr[N_NODES + 1];   // CSR row pointers
__device__ int   g_cursor[N_NODES];       // fill cursors
__device__ int   g_srcs[N_EDGES];         // CSR: src node per slot
__device__ float g_scale[N_EDGES];        // CSR: 1/edge_attr per slot
__device__ int   g_is32;                  // 1 if edge_index is int32, 0 if int64

// ---------------- dtype detection ----------------
// For int64 edge_index with values in [0, 40000), every odd 32-bit word is 0.
// For int32 edge_index, odd words are random node indices (P(all 4096 == 0) ~ 0).
__global__ void detect_kernel(const int* __restrict__ ei32) {
    int t = threadIdx.x;
    int nz = 0;
    for (int i = t; i < 4096; i += blockDim.x) {
        nz |= (ei32[2 * i + 1] != 0);
    }
    nz = __syncthreads_or(nz);
    if (t == 0) g_is32 = nz;
}

// ---------------- CSR build ----------------
__global__ void zero_deg_kernel() {
    int i = blockIdx.x * blockDim.x + threadIdx.x;
    if (i < N_NODES) g_deg[i] = 0;
}

__device__ __forceinline__ int load_idx(const void* ei, int pos) {
    if (g_is32) return ((const int*)ei)[pos];
    return (int)((const long long*)ei)[pos];
}

__global__ void count_kernel(const void* __restrict__ ei) {
    int e = blockIdx.x * blockDim.x + threadIdx.x;
    if (e >= N_EDGES) return;
    int dst = load_idx(ei, N_EDGES + e);
    if ((unsigned)dst < (unsigned)N_NODES) atomicAdd(&g_deg[dst], 1);
}

__global__ void scan_kernel() {
    // single block, 1024 threads; each thread handles a chunk of 40 nodes
    __shared__ int sums[1024];
    const int CH = 40;  // 1024*40 = 40960 >= 40000
    int t = threadIdx.x;
    int begin = t * CH;
    int end = begin + CH; if (end > N_NODES) end = N_NODES;
    if (begin > N_NODES) begin = N_NODES;
    int s = 0;
    for (int i = begin; i < end; i++) s += g_deg[i];
    sums[t] = s;
    __syncthreads();
    // Hillis-Steele inclusive scan
    for (int off = 1; off < 1024; off <<= 1) {
        int v = (t >= off) ? sums[t - off] : 0;
        __syncthreads();
        sums[t] += v;
        __syncthreads();
    }
    int run = (t == 0) ? 0 : sums[t - 1];
    for (int i = begin; i < end; i++) {
        g_rowptr[i] = run;
        g_cursor[i] = run;
        run += g_deg[i];
    }
    if (t == 1023) g_rowptr[N_NODES] = run;
}

__global__ void fill_kernel(const void* __restrict__ ei,
                            const float* __restrict__ ea) {
    int e = blockIdx.x * blockDim.x + threadIdx.x;
    if (e >= N_EDGES) return;
    int src = load_idx(ei, e);
    int dst = load_idx(ei, N_EDGES + e);
    if ((unsigned)dst >= (unsigned)N_NODES) return;
    if ((unsigned)src >= (unsigned)N_NODES) return;
    int pos = atomicAdd(&g_cursor[dst], 1);
    g_srcs[pos]  = src;
    g_scale[pos] = 1.0f / ea[e];
}

// ---------------- GEMM: g_h[m][n] = sum_k X[m][k] * W[n][k]  (h = x @ W.T) ----------------
// layer==0: X = x_ext (kernel arg). layer==1: X = g_y (device symbol).
// BM=128, BN=128(full), BK=16, 256 threads, 8x8 register tile per thread
__global__ __launch_bounds__(256) void gemm_nt_kernel(const float* __restrict__ x_ext,
                                                      const float* __restrict__ W,
                                                      int layer) {
    __shared__ float As[16][128];
    __shared__ float Bs[16][128];
    const float* X = (layer == 0) ? x_ext : (const float*)g_y;
    const int block_row = blockIdx.x * 128;
    const int tid = threadIdx.x;
    const int tx = tid & 15;   // col group (0..15) -> cols tx*8..tx*8+7
    const int ty = tid >> 4;   // row group (0..15) -> rows ty*8..ty*8+7

    float acc[8][8];
#pragma unroll
    for (int i = 0; i < 8; i++)
#pragma unroll
        for (int j = 0; j < 8; j++) acc[i][j] = 0.0f;

    for (int k0 = 0; k0 < 128; k0 += 16) {
#pragma unroll
        for (int it = 0; it < 2; it++) {
            int idx = tid + it * 256;          // 0..511
            int r = idx >> 2;                  // 0..127
            int c = (idx & 3) * 4;             // 0,4,8,12
            int gr = block_row + r;
            float4 v = make_float4(0.f, 0.f, 0.f, 0.f);
            if (gr < N_NODES) v = *reinterpret_cast<const float4*>(X + (size_t)gr * D + k0 + c);
            As[c + 0][r] = v.x; As[c + 1][r] = v.y; As[c + 2][r] = v.z; As[c + 3][r] = v.w;
        }
#pragma unroll
        for (int it = 0; it < 2; it++) {
            int idx = tid + it * 256;
            int r = idx >> 2;
            int c = (idx & 3) * 4;
            float4 v = *reinterpret_cast<const float4*>(W + (size_t)r * D + k0 + c);
            Bs[c + 0][r] = v.x; Bs[c + 1][r] = v.y; Bs[c + 2][r] = v.z; Bs[c + 3][r] = v.w;
        }
        __syncthreads();

#pragma unroll
        for (int k = 0; k < 16; k++) {
            float a[8], b[8];
#pragma unroll
            for (int i = 0; i < 8; i++) a[i] = As[k][ty * 8 + i];
#pragma unroll
            for (int j = 0; j < 8; j++) b[j] = Bs[k][tx * 8 + j];
#pragma unroll
            for (int i = 0; i < 8; i++)
#pragma unroll
                for (int j = 0; j < 8; j++) acc[i][j] += a[i] * b[j];
        }
        __syncthreads();
    }

#pragma unroll
    for (int i = 0; i < 8; i++) {
        int gr = block_row + ty * 8 + i;
        if (gr < N_NODES) {
            float4* o = reinterpret_cast<float4*>((float*)g_h + (size_t)gr * D + tx * 8);
            o[0] = make_float4(acc[i][0], acc[i][1], acc[i][2], acc[i][3]);
            o[1] = make_float4(acc[i][4], acc[i][5], acc[i][6], acc[i][7]);
        }
    }
}

// ---------------- aggregate: dst[n] = relu( sum_{e in CSR[n]} g_h[src_e]*scale_e + bias ) ----------------
// layer==0: write g_y (symbol). layer==1: write out_ext (kernel arg).
// one warp per node, each lane owns 4 contiguous features (float4)
__global__ __launch_bounds__(256) void agg_kernel(const float* __restrict__ bias,
                                                  float* __restrict__ out_ext,
                                                  int layer) {
    int warp = (blockIdx.x * blockDim.x + threadIdx.x) >> 5;
    int lane = threadIdx.x & 31;
    if (warp >= N_NODES) return;
    const float* H = (const float*)g_h;
    float* outp = (layer == 0) ? (float*)g_y : out_ext;
    int begin = g_rowptr[warp];
    int end   = g_rowptr[warp + 1];

    float4 acc = make_float4(0.f, 0.f, 0.f, 0.f);
    int i = begin;
    for (; i + 1 < end; i += 2) {
        int   s0 = g_srcs[i],     s1 = g_srcs[i + 1];
        float w0 = g_scale[i],    w1 = g_scale[i + 1];
        float4 v0 = *reinterpret_cast<const float4*>(H + (size_t)s0 * D + lane * 4);
        float4 v1 = *reinterpret_cast<const float4*>(H + (size_t)s1 * D + lane * 4);
        acc.x += w0 * v0.x; acc.y += w0 * v0.y; acc.z += w0 * v0.z; acc.w += w0 * v0.w;
        acc.x += w1 * v1.x; acc.y += w1 * v1.y; acc.z += w1 * v1.z; acc.w += w1 * v1.w;
    }
    if (i < end) {
        int   s0 = g_srcs[i];
        float w0 = g_scale[i];
        float4 v0 = *reinterpret_cast<const float4*>(H + (size_t)s0 * D + lane * 4);
        acc.x += w0 * v0.x; acc.y += w0 * v0.y; acc.z += w0 * v0.z; acc.w += w0 * v0.w;
    }

    float4 b = *reinterpret_cast<const float4*>(bias + lane * 4);
    float4 r;
    r.x = acc.x + b.x; r.x = r.x > 0.f ? r.x : 0.f;
    r.y = acc.y + b.y; r.y = r.y > 0.f ? r.y : 0.f;
    r.z = acc.z + b.z; r.z = r.z > 0.f ? r.z : 0.f;
    r.w = acc.w + b.w; r.w = r.w > 0.f ? r.w : 0.f;
    *reinterpret_cast<float4*>(outp + (size_t)warp * D + lane * 4) = r;
}

// ---------------- launch ----------------
extern "C" void kernel_launch(void* const* d_in, const int* in_sizes, int n_in,
                              void* d_out, int out_size) {
    const float* x  = (const float*)d_in[0];
    const void*  ei = d_in[1];                 // int32 or int64, auto-detected
    const float* ea = (const float*)d_in[2];
    const float* W1 = (const float*)d_in[3];
    const float* b1 = (const float*)d_in[4];
    const float* W2 = (const float*)d_in[5];
    const float* b2 = (const float*)d_in[6];
    float* out = (float*)d_out;

    // CSR build (shared by both layers)
    detect_kernel<<<1, 256>>>((const int*)ei);
    zero_deg_kernel<<<(N_NODES + 255) / 256, 256>>>();
    count_kernel<<<(N_EDGES + 255) / 256, 256>>>(ei);
    scan_kernel<<<1, 1024>>>();
    fill_kernel<<<(N_EDGES + 255) / 256, 256>>>(ei, ea);

    const int gemm_grid = (N_NODES + 127) / 128;        // 313
    const int agg_grid  = (N_NODES * 32 + 255) / 256;   // 5000 blocks (8 warps each)

    // layer 1: g_h = x @ W1^T ; g_y = relu(agg(g_h) + b1)
    gemm_nt_kernel<<<gemm_grid, 256>>>(x, W1, 0);
    agg_kernel<<<agg_grid, 256>>>(b1, out, 0);

    // layer 2: g_h = g_y @ W2^T ; out = relu(agg(g_h) + b2)
    gemm_nt_kernel<<<gemm_grid, 256>>>(x, W2, 1);
    agg_kernel<<<agg_grid, 256>>>(b2, out, 1);
}

// round 4
// speedup vs baseline: 1.3100x; 1.3100x over previous
#include <cuda_runtime.h>
#include <cuda_bf16.h>

#define N_NODES 40000
#define N_EDGES 640000
#define D 128
#define NB 157  // ceil(40000/256) scan blocks

// ---------------- scratch (device globals, referenced by symbol only) ----------------
__device__ float g_h[N_NODES * D];        // GEMM output (per layer)
__device__ float g_y[N_NODES * D];        // layer-1 output
__device__ int   g_deg[N_NODES];          // degree histogram (by dst)
__device__ int   g_rowptr[N_NODES + 1];   // CSR row pointers
__device__ int   g_cursor[N_NODES];       // fill cursors
__device__ int   g_srcs[N_EDGES];         // CSR: src node per slot
__device__ float g_scale[N_EDGES];        // CSR: 1/edge_attr per slot
__device__ int   g_is32;                  // 1 if edge_index is int32, 0 if int64
__device__ int   g_bsum[NB];              // per-block degree sums
__device__ int   g_boff[NB];              // exclusive block offsets

// ---------------- dtype detection ----------------
__global__ void detect_kernel(const int* __restrict__ ei32) {
    int t = threadIdx.x;
    int nz = 0;
    for (int i = t; i < 4096; i += blockDim.x) {
        nz |= (ei32[2 * i + 1] != 0);
    }
    nz = __syncthreads_or(nz);
    if (t == 0) g_is32 = nz;
}

// ---------------- CSR build ----------------
__global__ void zero_deg_kernel() {
    int i = blockIdx.x * blockDim.x + threadIdx.x;
    if (i < N_NODES) g_deg[i] = 0;
}

__device__ __forceinline__ int load_idx(const void* ei, int pos) {
    if (g_is32) return ((const int*)ei)[pos];
    return (int)((const long long*)ei)[pos];
}

__global__ void count_kernel(const void* __restrict__ ei) {
    int e = blockIdx.x * blockDim.x + threadIdx.x;
    if (e >= N_EDGES) return;
    int dst = load_idx(ei, N_EDGES + e);
    if ((unsigned)dst < (unsigned)N_NODES) atomicAdd(&g_deg[dst], 1);
}

// ---- scan phase 1: per-block sums (grid=NB, 256 threads) ----
__global__ __launch_bounds__(256) void bsum_kernel() {
    int i = blockIdx.x * 256 + threadIdx.x;
    int v = (i < N_NODES) ? g_deg[i] : 0;
#pragma unroll
    for (int off = 16; off > 0; off >>= 1)
        v += __shfl_down_sync(0xffffffffu, v, off);
    __shared__ int ws[8];
    int wid = threadIdx.x >> 5, lane = threadIdx.x & 31;
    if (lane == 0) ws[wid] = v;
    __syncthreads();
    if (threadIdx.x == 0) {
        int s = 0;
#pragma unroll
        for (int w = 0; w < 8; w++) s += ws[w];
        g_bsum[blockIdx.x] = s;
    }
}

// ---- scan phase 2: exclusive scan of NB block sums (1 block, 256 threads) ----
__global__ __launch_bounds__(256) void bscan_kernel() {
    int t = threadIdx.x;
    int lane = t & 31, wid = t >> 5;
    int v = (t < NB) ? g_bsum[t] : 0;
    int orig = v;
    // warp inclusive scan
#pragma unroll
    for (int off = 1; off < 32; off <<= 1) {
        int u = __shfl_up_sync(0xffffffffu, v, off);
        if (lane >= off) v += u;
    }
    __shared__ int wsum[8];
    if (lane == 31) wsum[wid] = v;
    __syncthreads();
    if (wid == 0) {
        int s = (lane < 8) ? wsum[lane] : 0;
#pragma unroll
        for (int off = 1; off < 8; off <<= 1) {
            int u = __shfl_up_sync(0xffffffffu, s, off);
            if (lane >= off) s += u;
        }
        if (lane < 8) wsum[lane] = s;
    }
    __syncthreads();
    int incl = v + (wid > 0 ? wsum[wid - 1] : 0);
    if (t < NB) g_boff[t] = incl - orig;  // exclusive
}

// ---- scan phase 3: intra-block exclusive scan + write rowptr/cursor ----
__global__ __launch_bounds__(256) void rowptr_kernel() {
    int i = blockIdx.x * 256 + threadIdx.x;
    int lane = threadIdx.x & 31, wid = threadIdx.x >> 5;
    int v = (i < N_NODES) ? g_deg[i] : 0;
    int orig = v;
#pragma unroll
    for (int off = 1; off < 32; off <<= 1) {
        int u = __shfl_up_sync(0xffffffffu, v, off);
        if (lane >= off) v += u;
    }
    __shared__ int wsum[8];
    if (lane == 31) wsum[wid] = v;
    __syncthreads();
    if (wid == 0) {
        int s = (lane < 8) ? wsum[lane] : 0;
#pragma unroll
        for (int off = 1; off < 8; off <<= 1) {
            int u = __shfl_up_sync(0xffffffffu, s, off);
            if (lane >= off) s += u;
        }
        if (lane < 8) wsum[lane] = s;
    }
    __syncthreads();
    int incl = v + (wid > 0 ? wsum[wid - 1] : 0);
    int excl = incl - orig + g_boff[blockIdx.x];
    if (i < N_NODES) {
        g_rowptr[i] = excl;
        g_cursor[i] = excl;
        if (i == N_NODES - 1) g_rowptr[N_NODES] = excl + orig;
    }
}

__global__ void fill_kernel(const void* __restrict__ ei,
                            const float* __restrict__ ea) {
    int e = blockIdx.x * blockDim.x + threadIdx.x;
    if (e >= N_EDGES) return;
    int src = load_idx(ei, e);
    int dst = load_idx(ei, N_EDGES + e);
    if ((unsigned)dst >= (unsigned)N_NODES) return;
    if ((unsigned)src >= (unsigned)N_NODES) return;
    int pos = atomicAdd(&g_cursor[dst], 1);
    g_srcs[pos]  = src;
    g_scale[pos] = 1.0f / ea[e];
}

// ---------------- GEMM: g_h[m][n] = sum_k X[m][k] * W[n][k]  (h = x @ W.T) ----------------
__global__ __launch_bounds__(256) void gemm_nt_kernel(const float* __restrict__ x_ext,
                                                      const float* __restrict__ W,
                                                      int layer) {
    __shared__ float As[16][128];
    __shared__ float Bs[16][128];
    const float* X = (layer == 0) ? x_ext : (const float*)g_y;
    const int block_row = blockIdx.x * 128;
    const int tid = threadIdx.x;
    const int tx = tid & 15;
    const int ty = tid >> 4;

    float acc[8][8];
#pragma unroll
    for (int i = 0; i < 8; i++)
#pragma unroll
        for (int j = 0; j < 8; j++) acc[i][j] = 0.0f;

    for (int k0 = 0; k0 < 128; k0 += 16) {
#pragma unroll
        for (int it = 0; it < 2; it++) {
            int idx = tid + it * 256;
            int r = idx >> 2;
            int c = (idx & 3) * 4;
            int gr = block_row + r;
            float4 v = make_float4(0.f, 0.f, 0.f, 0.f);
            if (gr < N_NODES) v = *reinterpret_cast<const float4*>(X + (size_t)gr * D + k0 + c);
            As[c + 0][r] = v.x; As[c + 1][r] = v.y; As[c + 2][r] = v.z; As[c + 3][r] = v.w;
        }
#pragma unroll
        for (int it = 0; it < 2; it++) {
            int idx = tid + it * 256;
            int r = idx >> 2;
            int c = (idx & 3) * 4;
            float4 v = *reinterpret_cast<const float4*>(W + (size_t)r * D + k0 + c);
            Bs[c + 0][r] = v.x; Bs[c + 1][r] = v.y; Bs[c + 2][r] = v.z; Bs[c + 3][r] = v.w;
        }
        __syncthreads();

#pragma unroll
        for (int k = 0; k < 16; k++) {
            float a[8], b[8];
#pragma unroll
            for (int i = 0; i < 8; i++) a[i] = As[k][ty * 8 + i];
#pragma unroll
            for (int j = 0; j < 8; j++) b[j] = Bs[k][tx * 8 + j];
#pragma unroll
            for (int i = 0; i < 8; i++)
#pragma unroll
                for (int j = 0; j < 8; j++) acc[i][j] += a[i] * b[j];
        }
        __syncthreads();
    }

#pragma unroll
    for (int i = 0; i < 8; i++) {
        int gr = block_row + ty * 8 + i;
        if (gr < N_NODES) {
            float4* o = reinterpret_cast<float4*>((float*)g_h + (size_t)gr * D + tx * 8);
            o[0] = make_float4(acc[i][0], acc[i][1], acc[i][2], acc[i][3]);
            o[1] = make_float4(acc[i][4], acc[i][5], acc[i][6], acc[i][7]);
        }
    }
}

// ---------------- aggregate: dst[n] = relu( sum_{e in CSR[n]} g_h[src_e]*scale_e + bias ) ----------------
__global__ __launch_bounds__(256) void agg_kernel(const float* __restrict__ bias,
                                                  float* __restrict__ out_ext,
                                                  int layer) {
    int warp = (blockIdx.x * blockDim.x + threadIdx.x) >> 5;
    int lane = threadIdx.x & 31;
    if (warp >= N_NODES) return;
    const float* H = (const float*)g_h;
    float* outp = (layer == 0) ? (float*)g_y : out_ext;
    int begin = g_rowptr[warp];
    int end   = g_rowptr[warp + 1];

    float4 acc = make_float4(0.f, 0.f, 0.f, 0.f);
    int i = begin;
    for (; i + 1 < end; i += 2) {
        int   s0 = g_srcs[i],     s1 = g_srcs[i + 1];
        float w0 = g_scale[i],    w1 = g_scale[i + 1];
        float4 v0 = *reinterpret_cast<const float4*>(H + (size_t)s0 * D + lane * 4);
        float4 v1 = *reinterpret_cast<const float4*>(H + (size_t)s1 * D + lane * 4);
        acc.x += w0 * v0.x; acc.y += w0 * v0.y; acc.z += w0 * v0.z; acc.w += w0 * v0.w;
        acc.x += w1 * v1.x; acc.y += w1 * v1.y; acc.z += w1 * v1.z; acc.w += w1 * v1.w;
    }
    if (i < end) {
        int   s0 = g_srcs[i];
        float w0 = g_scale[i];
        float4 v0 = *reinterpret_cast<const float4*>(H + (size_t)s0 * D + lane * 4);
        acc.x += w0 * v0.x; acc.y += w0 * v0.y; acc.z += w0 * v0.z; acc.w += w0 * v0.w;
    }

    float4 b = *reinterpret_cast<const float4*>(bias + lane * 4);
    float4 r;
    r.x = acc.x + b.x; r.x = r.x > 0.f ? r.x : 0.f;
    r.y = acc.y + b.y; r.y = r.y > 0.f ? r.y : 0.f;
    r.z = acc.z + b.z; r.z = r.z > 0.f ? r.z : 0.f;
    r.w = acc.w + b.w; r.w = r.w > 0.f ? r.w : 0.f;
    *reinterpret_cast<float4*>(outp + (size_t)warp * D + lane * 4) = r;
}

// ---------------- launch ----------------
extern "C" void kernel_launch(void* const* d_in, const int* in_sizes, int n_in,
                              void* d_out, int out_size) {
    const float* x  = (const float*)d_in[0];
    const void*  ei = d_in[1];                 // int32 or int64, auto-detected
    const float* ea = (const float*)d_in[2];
    const float* W1 = (const float*)d_in[3];
    const float* b1 = (const float*)d_in[4];
    const float* W2 = (const float*)d_in[5];
    const float* b2 = (const float*)d_in[6];
    float* out = (float*)d_out;

    // CSR build (shared by both layers)
    detect_kernel<<<1, 256>>>((const int*)ei);
    zero_deg_kernel<<<(N_NODES + 255) / 256, 256>>>();
    count_kernel<<<(N_EDGES + 255) / 256, 256>>>(ei);
    bsum_kernel<<<NB, 256>>>();
    bscan_kernel<<<1, 256>>>();
    rowptr_kernel<<<NB, 256>>>();
    fill_kernel<<<(N_EDGES + 255) / 256, 256>>>(ei, ea);

    const int gemm_grid = (N_NODES + 127) / 128;        // 313
    const int agg_grid  = (N_NODES * 32 + 255) / 256;   // 5000 blocks (8 warps each)

    // layer 1: g_h = x @ W1^T ; g_y = relu(agg(g_h) + b1)
    gemm_nt_kernel<<<gemm_grid, 256>>>(x, W1, 0);
    agg_kernel<<<agg_grid, 256>>>(b1, out, 0);

    // layer 2: g_h = g_y @ W2^T ; out = relu(agg(g_h) + b2)
    gemm_nt_kernel<<<gemm_grid, 256>>>(x, W2, 1);
    agg_kernel<<<agg_grid, 256>>>(b2, out, 1);
}

// round 5
// speedup vs baseline: 1.3515x; 1.0317x over previous
#include <cuda_runtime.h>
#include <cuda_bf16.h>

#define N_NODES 40000
#define N_EDGES 640000
#define D 128
#define NB 157  // ceil(40000/256) scan blocks

// ---------------- scratch (device globals, referenced by symbol only) ----------------
__device__ float g_h[N_NODES * D];        // GEMM output (per layer)
__device__ float g_y[N_NODES * D];        // layer-1 output
__device__ int   g_deg[N_NODES];          // degree histogram (by dst)
__device__ int   g_rowptr[N_NODES + 1];   // CSR row pointers
__device__ int   g_cursor[N_NODES];       // fill cursors
__device__ int   g_srcs[N_EDGES];         // CSR: src node per slot
__device__ float g_scale[N_EDGES];        // CSR: 1/edge_attr per slot
__device__ int   g_is32;                  // 1 if edge_index is int32, 0 if int64
__device__ int   g_bsum[NB];              // per-block degree sums
__device__ int   g_boff[NB];              // exclusive block offsets

// ---------------- init: zero degree histogram + detect edge_index dtype ----------------
// int64 edge_index with values < 40000 has every odd 32-bit word == 0;
// int32 edge_index has random indices there.
__global__ __launch_bounds__(256) void init_kernel(const int* __restrict__ ei32) {
    int i = blockIdx.x * 256 + threadIdx.x;
    if (i < N_NODES) g_deg[i] = 0;
    if (blockIdx.x == 0) {
        int nz = 0;
        for (int s = threadIdx.x; s < 4096; s += 256)
            nz |= (ei32[2 * s + 1] != 0);
        nz = __syncthreads_or(nz);
        if (threadIdx.x == 0) g_is32 = nz;
    }
}

__device__ __forceinline__ int load_idx(const void* ei, int pos) {
    if (g_is32) return ((const int*)ei)[pos];
    return (int)((const long long*)ei)[pos];
}

__global__ void count_kernel(const void* __restrict__ ei) {
    int e = blockIdx.x * blockDim.x + threadIdx.x;
    if (e >= N_EDGES) return;
    int dst = load_idx(ei, N_EDGES + e);
    if ((unsigned)dst < (unsigned)N_NODES) atomicAdd(&g_deg[dst], 1);
}

// ---- scan phase 1: per-block sums ----
__global__ __launch_bounds__(256) void bsum_kernel() {
    int i = blockIdx.x * 256 + threadIdx.x;
    int v = (i < N_NODES) ? g_deg[i] : 0;
#pragma unroll
    for (int off = 16; off > 0; off >>= 1)
        v += __shfl_down_sync(0xffffffffu, v, off);
    __shared__ int ws[8];
    int wid = threadIdx.x >> 5, lane = threadIdx.x & 31;
    if (lane == 0) ws[wid] = v;
    __syncthreads();
    if (threadIdx.x == 0) {
        int s = 0;
#pragma unroll
        for (int w = 0; w < 8; w++) s += ws[w];
        g_bsum[blockIdx.x] = s;
    }
}

// ---- scan phase 2: exclusive scan of NB block sums ----
__global__ __launch_bounds__(256) void bscan_kernel() {
    int t = threadIdx.x;
    int lane = t & 31, wid = t >> 5;
    int v = (t < NB) ? g_bsum[t] : 0;
    int orig = v;
#pragma unroll
    for (int off = 1; off < 32; off <<= 1) {
        int u = __shfl_up_sync(0xffffffffu, v, off);
        if (lane >= off) v += u;
    }
    __shared__ int wsum[8];
    if (lane == 31) wsum[wid] = v;
    __syncthreads();
    if (wid == 0) {
        int s = (lane < 8) ? wsum[lane] : 0;
#pragma unroll
        for (int off = 1; off < 8; off <<= 1) {
            int u = __shfl_up_sync(0xffffffffu, s, off);
            if (lane >= off) s += u;
        }
        if (lane < 8) wsum[lane] = s;
    }
    __syncthreads();
    int incl = v + (wid > 0 ? wsum[wid - 1] : 0);
    if (t < NB) g_boff[t] = incl - orig;
}

// ---- scan phase 3: intra-block exclusive scan + write rowptr/cursor ----
__global__ __launch_bounds__(256) void rowptr_kernel() {
    int i = blockIdx.x * 256 + threadIdx.x;
    int lane = threadIdx.x & 31, wid = threadIdx.x >> 5;
    int v = (i < N_NODES) ? g_deg[i] : 0;
    int orig = v;
#pragma unroll
    for (int off = 1; off < 32; off <<= 1) {
        int u = __shfl_up_sync(0xffffffffu, v, off);
        if (lane >= off) v += u;
    }
    __shared__ int wsum[8];
    if (lane == 31) wsum[wid] = v;
    __syncthreads();
    if (wid == 0) {
        int s = (lane < 8) ? wsum[lane] : 0;
#pragma unroll
        for (int off = 1; off < 8; off <<= 1) {
            int u = __shfl_up_sync(0xffffffffu, s, off);
            if (lane >= off) s += u;
        }
        if (lane < 8) wsum[lane] = s;
    }
    __syncthreads();
    int incl = v + (wid > 0 ? wsum[wid - 1] : 0);
    int excl = incl - orig + g_boff[blockIdx.x];
    if (i < N_NODES) {
        g_rowptr[i] = excl;
        g_cursor[i] = excl;
        if (i == N_NODES - 1) g_rowptr[N_NODES] = excl + orig;
    }
}

__global__ void fill_kernel(const void* __restrict__ ei,
                            const float* __restrict__ ea) {
    int e = blockIdx.x * blockDim.x + threadIdx.x;
    if (e >= N_EDGES) return;
    int src = load_idx(ei, e);
    int dst = load_idx(ei, N_EDGES + e);
    if ((unsigned)dst >= (unsigned)N_NODES) return;
    if ((unsigned)src >= (unsigned)N_NODES) return;
    int pos = atomicAdd(&g_cursor[dst], 1);
    g_srcs[pos]  = src;
    g_scale[pos] = 1.0f / ea[e];
}

// ---------------- GEMM via packed fma.rn.f32x2 (FFMA2): g_h = X @ W^T ----------------
// acc pairs adjacent output columns in one 64-bit register; exact fp32 semantics.
__global__ __launch_bounds__(256, 2) void gemm_nt_kernel(const float* __restrict__ x_ext,
                                                         const float* __restrict__ W,
                                                         int layer) {
    __shared__ __align__(16) float As[16][128];
    __shared__ __align__(16) float Bs[16][128];
    const float* X = (layer == 0) ? x_ext : (const float*)g_y;
    const int block_row = blockIdx.x * 128;
    const int tid = threadIdx.x;
    const int tx = tid & 15;   // col group: cols tx*8 .. tx*8+7
    const int ty = tid >> 4;   // row group: rows ty*8 .. ty*8+7

    unsigned long long acc2[8][4];
#pragma unroll
    for (int i = 0; i < 8; i++)
#pragma unroll
        for (int j = 0; j < 4; j++) acc2[i][j] = 0ull;

    for (int k0 = 0; k0 < 128; k0 += 16) {
#pragma unroll
        for (int it = 0; it < 2; it++) {
            int idx = tid + it * 256;
            int r = idx >> 2;
            int c = (idx & 3) * 4;
            int gr = block_row + r;
            float4 v = make_float4(0.f, 0.f, 0.f, 0.f);
            if (gr < N_NODES) v = *reinterpret_cast<const float4*>(X + (size_t)gr * D + k0 + c);
            As[c + 0][r] = v.x; As[c + 1][r] = v.y; As[c + 2][r] = v.z; As[c + 3][r] = v.w;
        }
#pragma unroll
        for (int it = 0; it < 2; it++) {
            int idx = tid + it * 256;
            int r = idx >> 2;
            int c = (idx & 3) * 4;
            float4 v = *reinterpret_cast<const float4*>(W + (size_t)r * D + k0 + c);
            Bs[c + 0][r] = v.x; Bs[c + 1][r] = v.y; Bs[c + 2][r] = v.z; Bs[c + 3][r] = v.w;
        }
        __syncthreads();

#pragma unroll
        for (int k = 0; k < 16; k++) {
            unsigned long long a2[8], b2[4];
#pragma unroll
            for (int i = 0; i < 8; i++) {
                unsigned int av = __float_as_uint(As[k][ty * 8 + i]);
                asm("mov.b64 %0, {%1, %1};" : "=l"(a2[i]) : "r"(av));
            }
#pragma unroll
            for (int j = 0; j < 4; j++)
                b2[j] = *reinterpret_cast<const unsigned long long*>(&Bs[k][tx * 8 + 2 * j]);
#pragma unroll
            for (int i = 0; i < 8; i++)
#pragma unroll
                for (int j = 0; j < 4; j++)
                    asm("fma.rn.f32x2 %0, %1, %2, %0;" : "+l"(acc2[i][j]) : "l"(a2[i]), "l"(b2[j]));
        }
        __syncthreads();
    }

#pragma unroll
    for (int i = 0; i < 8; i++) {
        int gr = block_row + ty * 8 + i;
        if (gr < N_NODES) {
            float o[8];
#pragma unroll
            for (int j = 0; j < 4; j++) {
                unsigned int lo, hi;
                asm("mov.b64 {%0, %1}, %2;" : "=r"(lo), "=r"(hi) : "l"(acc2[i][j]));
                o[2 * j]     = __uint_as_float(lo);
                o[2 * j + 1] = __uint_as_float(hi);
            }
            float4* op = reinterpret_cast<float4*>((float*)g_h + (size_t)gr * D + tx * 8);
            op[0] = make_float4(o[0], o[1], o[2], o[3]);
            op[1] = make_float4(o[4], o[5], o[6], o[7]);
        }
    }
}

// ---------------- aggregate: dst[n] = relu( sum_{e in CSR[n]} g_h[src_e]*scale_e + bias ) ----------------
__global__ __launch_bounds__(256) void agg_kernel(const float* __restrict__ bias,
                                                  float* __restrict__ out_ext,
                                                  int layer) {
    int warp = (blockIdx.x * blockDim.x + threadIdx.x) >> 5;
    int lane = threadIdx.x & 31;
    if (warp >= N_NODES) return;
    const float* H = (const float*)g_h;
    float* outp = (layer == 0) ? (float*)g_y : out_ext;
    int begin = g_rowptr[warp];
    int end   = g_rowptr[warp + 1];

    float4 acc = make_float4(0.f, 0.f, 0.f, 0.f);
    int i = begin;
    for (; i + 1 < end; i += 2) {
        int   s0 = g_srcs[i],     s1 = g_srcs[i + 1];
        float w0 = g_scale[i],    w1 = g_scale[i + 1];
        float4 v0 = *reinterpret_cast<const float4*>(H + (size_t)s0 * D + lane * 4);
        float4 v1 = *reinterpret_cast<const float4*>(H + (size_t)s1 * D + lane * 4);
        acc.x += w0 * v0.x; acc.y += w0 * v0.y; acc.z += w0 * v0.z; acc.w += w0 * v0.w;
        acc.x += w1 * v1.x; acc.y += w1 * v1.y; acc.z += w1 * v1.z; acc.w += w1 * v1.w;
    }
    if (i < end) {
        int   s0 = g_srcs[i];
        float w0 = g_scale[i];
        float4 v0 = *reinterpret_cast<const float4*>(H + (size_t)s0 * D + lane * 4);
        acc.x += w0 * v0.x; acc.y += w0 * v0.y; acc.z += w0 * v0.z; acc.w += w0 * v0.w;
    }

    float4 b = *reinterpret_cast<const float4*>(bias + lane * 4);
    float4 r;
    r.x = acc.x + b.x; r.x = r.x > 0.f ? r.x : 0.f;
    r.y = acc.y + b.y; r.y = r.y > 0.f ? r.y : 0.f;
    r.z = acc.z + b.z; r.z = r.z > 0.f ? r.z : 0.f;
    r.w = acc.w + b.w; r.w = r.w > 0.f ? r.w : 0.f;
    *reinterpret_cast<float4*>(outp + (size_t)warp * D + lane * 4) = r;
}

// ---------------- launch ----------------
extern "C" void kernel_launch(void* const* d_in, const int* in_sizes, int n_in,
                              void* d_out, int out_size) {
    const float* x  = (const float*)d_in[0];
    const void*  ei = d_in[1];                 // int32 or int64, auto-detected
    const float* ea = (const float*)d_in[2];
    const float* W1 = (const float*)d_in[3];
    const float* b1 = (const float*)d_in[4];
    const float* W2 = (const float*)d_in[5];
    const float* b2 = (const float*)d_in[6];
    float* out = (float*)d_out;

    const int gemm_grid = (N_NODES + 127) / 128;        // 313
    const int agg_grid  = (N_NODES * 32 + 255) / 256;   // 5000 blocks

    // launch idx:      0            1      2     3(profiled) 4      5       6     7     8     9
    init_kernel<<<NB, 256>>>((const int*)ei);                       // 0
    count_kernel<<<(N_EDGES + 255) / 256, 256>>>(ei);               // 1
    bsum_kernel<<<NB, 256>>>();                                     // 2
    gemm_nt_kernel<<<gemm_grid, 256>>>(x, W1, 0);                   // 3  <- profiled slot
    bscan_kernel<<<1, 256>>>();                                     // 4
    rowptr_kernel<<<NB, 256>>>();                                   // 5
    fill_kernel<<<(N_EDGES + 255) / 256, 256>>>(ei, ea);            // 6
    agg_kernel<<<agg_grid, 256>>>(b1, out, 0);                      // 7
    gemm_nt_kernel<<<gemm_grid, 256>>>(x, W2, 1);                   // 8
    agg_kernel<<<agg_grid, 256>>>(b2, out, 1);                      // 9
}